// round 2
// baseline (speedup 1.0000x reference)
#include <cuda_runtime.h>
#include <math.h>

// Problem shape (fixed by the dataset): B=4096 rows, N=32768 cols.
#define NCE_B 4096

// Scratch for per-row losses (no cudaMalloc allowed).
__device__ float g_row_loss[NCE_B];

// ---------------------------------------------------------------------------
// Kernel 1: one CTA per row. Streams scores+labels with float4 loads,
// computes e = exp(sigmoid(s)/T) with 3 MUFU ops, reduces (num, den),
// writes -log(num/(den+eps)+eps) per row.
// ---------------------------------------------------------------------------
__global__ __launch_bounds__(256) void nce_row_kernel(
    const float4* __restrict__ scores,
    const float4* __restrict__ labels,
    int n4)  // N/4 per row
{
    const int row = blockIdx.x;
    const float4* __restrict__ s = scores + (size_t)row * n4;
    const float4* __restrict__ l = labels + (size_t)row * n4;

    // exp(sig/T) = exp2(sig * (1/T)*log2(e)),  (1/0.07)*log2(e) = 20.609929...
    const float KE = 20.60992915555662f;
    const float L2E = 1.4426950408889634f;

    float num = 0.0f, den = 0.0f;

    #pragma unroll 4
    for (int i = threadIdx.x; i < n4; i += 256) {
        float4 sv = s[i];
        float4 lv = l[i];
        {
            float t = exp2f(-L2E * sv.x);
            float sg = __fdividef(1.0f, 1.0f + t);
            float e = exp2f(KE * sg);
            den += e; num += e * lv.x;
        }
        {
            float t = exp2f(-L2E * sv.y);
            float sg = __fdividef(1.0f, 1.0f + t);
            float e = exp2f(KE * sg);
            den += e; num += e * lv.y;
        }
        {
            float t = exp2f(-L2E * sv.z);
            float sg = __fdividef(1.0f, 1.0f + t);
            float e = exp2f(KE * sg);
            den += e; num += e * lv.z;
        }
        {
            float t = exp2f(-L2E * sv.w);
            float sg = __fdividef(1.0f, 1.0f + t);
            float e = exp2f(KE * sg);
            den += e; num += e * lv.w;
        }
    }

    // Warp reduction
    #pragma unroll
    for (int off = 16; off > 0; off >>= 1) {
        num += __shfl_xor_sync(0xffffffffu, num, off);
        den += __shfl_xor_sync(0xffffffffu, den, off);
    }

    __shared__ float s_num[8];
    __shared__ float s_den[8];
    const int lane = threadIdx.x & 31;
    const int wid  = threadIdx.x >> 5;
    if (lane == 0) { s_num[wid] = num; s_den[wid] = den; }
    __syncthreads();

    if (wid == 0) {
        float n2 = (lane < 8) ? s_num[lane] : 0.0f;
        float d2 = (lane < 8) ? s_den[lane] : 0.0f;
        #pragma unroll
        for (int off = 4; off > 0; off >>= 1) {
            n2 += __shfl_xor_sync(0xffffffffu, n2, off);
            d2 += __shfl_xor_sync(0xffffffffu, d2, off);
        }
        if (lane == 0) {
            float ratio = n2 / (d2 + 1e-12f) + 1e-12f;
            g_row_loss[row] = -logf(ratio);
        }
    }
}

// ---------------------------------------------------------------------------
// Kernel 2: deterministic mean over the 4096 per-row losses. One CTA.
// ---------------------------------------------------------------------------
__global__ __launch_bounds__(1024) void nce_mean_kernel(float* __restrict__ out)
{
    float s = 0.0f;
    #pragma unroll
    for (int i = threadIdx.x; i < NCE_B; i += 1024) s += g_row_loss[i];

    #pragma unroll
    for (int off = 16; off > 0; off >>= 1)
        s += __shfl_xor_sync(0xffffffffu, s, off);

    __shared__ float sw[32];
    const int lane = threadIdx.x & 31;
    const int wid  = threadIdx.x >> 5;
    if (lane == 0) sw[wid] = s;
    __syncthreads();

    if (wid == 0) {
        float v = (lane < 32) ? sw[lane] : 0.0f;
        #pragma unroll
        for (int off = 16; off > 0; off >>= 1)
            v += __shfl_xor_sync(0xffffffffu, v, off);
        if (lane == 0) *out = v * (1.0f / (float)NCE_B);
    }
}

extern "C" void kernel_launch(void* const* d_in, const int* in_sizes, int n_in,
                              void* d_out, int out_size)
{
    const float4* scores = (const float4*)d_in[0];
    const float4* labels = (const float4*)d_in[1];
    float* out = (float*)d_out;

    const int total = in_sizes[0];       // B * N
    const int n = total / NCE_B;         // N = 32768
    const int n4 = n / 4;                // float4 count per row

    nce_row_kernel<<<NCE_B, 256>>>(scores, labels, n4);
    nce_mean_kernel<<<1, 1024>>>(out);
}

// round 3
// speedup vs baseline: 1.0099x; 1.0099x over previous
#include <cuda_runtime.h>
#include <math.h>

// Problem shape (fixed by the dataset): B=4096 rows, N=32768 cols.
#define NCE_B 4096

// Scratch (no cudaMalloc allowed). Zero-initialized at module load.
__device__ float g_row_loss[NCE_B];
__device__ unsigned int g_ticket = 0;   // last-block fusion counter; reset by last block each call

__device__ __forceinline__ float tanh_approx(float x) {
    float y;
    asm("tanh.approx.f32 %0, %1;" : "=f"(y) : "f"(x));
    return y;
}

// ---------------------------------------------------------------------------
// One CTA per row. Streams scores+labels with float4 .cs loads,
// e = exp(sigmoid(s)/T) via 2 MUFU ops:
//   sig      = 0.5 + 0.5*tanh(0.5*s)
//   e        = exp2(KE*sig) = exp2(KH + KH*tanh(0.5*s)),  KH = 0.5*(1/T)*log2(e)
// Row loss -> g_row_loss; last CTA reduces the mean (deterministic order).
// ---------------------------------------------------------------------------
__global__ __launch_bounds__(256) void nce_fused_kernel(
    const float4* __restrict__ scores,
    const float4* __restrict__ labels,
    float* __restrict__ out,
    int n4)  // N/4 per row
{
    const int row = blockIdx.x;
    const float4* __restrict__ s = scores + (size_t)row * n4;
    const float4* __restrict__ l = labels + (size_t)row * n4;

    const float KH = 10.30496457777831f;  // 0.5 * (1/0.07) * log2(e)

    float num = 0.0f, den = 0.0f;

    #pragma unroll 4
    for (int i = threadIdx.x; i < n4; i += 256) {
        float4 sv = __ldcs(s + i);
        float4 lv = __ldcs(l + i);
        {
            float th = tanh_approx(0.5f * sv.x);
            float e  = exp2f(fmaf(KH, th, KH));
            den += e; num = fmaf(e, lv.x, num);
        }
        {
            float th = tanh_approx(0.5f * sv.y);
            float e  = exp2f(fmaf(KH, th, KH));
            den += e; num = fmaf(e, lv.y, num);
        }
        {
            float th = tanh_approx(0.5f * sv.z);
            float e  = exp2f(fmaf(KH, th, KH));
            den += e; num = fmaf(e, lv.z, num);
        }
        {
            float th = tanh_approx(0.5f * sv.w);
            float e  = exp2f(fmaf(KH, th, KH));
            den += e; num = fmaf(e, lv.w, num);
        }
    }

    // Warp reduction
    #pragma unroll
    for (int off = 16; off > 0; off >>= 1) {
        num += __shfl_xor_sync(0xffffffffu, num, off);
        den += __shfl_xor_sync(0xffffffffu, den, off);
    }

    __shared__ float s_num[8];
    __shared__ float s_den[8];
    __shared__ bool  s_last;
    const int lane = threadIdx.x & 31;
    const int wid  = threadIdx.x >> 5;
    if (lane == 0) { s_num[wid] = num; s_den[wid] = den; }
    __syncthreads();

    if (wid == 0) {
        float n2 = (lane < 8) ? s_num[lane] : 0.0f;
        float d2 = (lane < 8) ? s_den[lane] : 0.0f;
        #pragma unroll
        for (int off = 4; off > 0; off >>= 1) {
            n2 += __shfl_xor_sync(0xffffffffu, n2, off);
            d2 += __shfl_xor_sync(0xffffffffu, d2, off);
        }
        if (lane == 0) {
            float ratio = n2 / (d2 + 1e-12f) + 1e-12f;
            g_row_loss[row] = -logf(ratio);
            __threadfence();
            unsigned int t = atomicAdd(&g_ticket, 1u);
            s_last = (t == (unsigned int)(gridDim.x - 1));
        }
    }
    __syncthreads();

    // Last CTA to finish: reduce the mean over all rows (fixed read order
    // -> deterministic), write result, reset ticket for the next replay.
    if (s_last) {
        float acc = 0.0f;
        #pragma unroll
        for (int i = threadIdx.x; i < NCE_B; i += 256) acc += g_row_loss[i];

        #pragma unroll
        for (int off = 16; off > 0; off >>= 1)
            acc += __shfl_xor_sync(0xffffffffu, acc, off);

        if (lane == 0) { s_num[wid] = acc; }
        __syncthreads();
        if (wid == 0) {
            float v = (lane < 8) ? s_num[lane] : 0.0f;
            #pragma unroll
            for (int off = 4; off > 0; off >>= 1)
                v += __shfl_xor_sync(0xffffffffu, v, off);
            if (lane == 0) {
                *out = v * (1.0f / (float)NCE_B);
                g_ticket = 0;          // restore state for next graph replay
                __threadfence();
            }
        }
    }
}

extern "C" void kernel_launch(void* const* d_in, const int* in_sizes, int n_in,
                              void* d_out, int out_size)
{
    const float4* scores = (const float4*)d_in[0];
    const float4* labels = (const float4*)d_in[1];
    float* out = (float*)d_out;

    const int total = in_sizes[0];       // B * N
    const int n = total / NCE_B;         // N = 32768
    const int n4 = n / 4;                // float4 count per row

    nce_fused_kernel<<<NCE_B, 256>>>(scores, labels, out, n4);
}